// round 12
// baseline (speedup 1.0000x reference)
#include <cuda_runtime.h>
#include <stdint.h>
#include <math.h>

#define NN   10000
#define EE   320000
#define HIDD 128
#define NH   4
#define NL   2
#define NEG  0.2f
#define BNEPS 1e-5f

// ---------------- scratch ----------------
__device__ float g_h[NN * HIDD];
__device__ float g_agg[NN * HIDD * NH];     // aggregated h per head: [n][h*128+c]
__device__ float g_outp[NN * HIDD];
__device__ float g_ae[EE * 8];              // [E][L][H]
__device__ float g_aeloop[NN * 8];
__device__ float g_asrc[NN * NH];
__device__ float g_adst[NN * NH];
__device__ int   g_deg[NN];
__device__ int   g_rowptr[NN + 1];
__device__ int   g_fill[NN];
__device__ int   g_col[EE];
__device__ float g_ve[NL * HIDD * NH];      // We . att_edge
__device__ float g_ue[NL * 64 * NH];        // eenc_W @ ve
__device__ float g_ce[NL * NH];
__device__ float g_wsd[NL * HIDD * 8];      // W . att_src / att_dst  [L][128][8]
__device__ float g_Wp[NL * 512 * HIDD];     // permuted W: [l][(h*128+c)][c']
__device__ float g_bnsum[HIDD];
__device__ float g_bnsq[HIDD];

// ---------------- tf32 helpers ----------------
__device__ __forceinline__ uint32_t f2tf32(float f) {
    uint32_t u; asm("cvt.rna.tf32.f32 %0, %1;" : "=r"(u) : "f"(f)); return u;
}
__device__ __forceinline__ void mma8(float* c, const uint32_t* a, uint32_t b0, uint32_t b1) {
    asm("mma.sync.aligned.m16n8k8.row.col.f32.tf32.tf32.f32 "
        "{%0,%1,%2,%3},{%4,%5,%6,%7},{%8,%9},{%0,%1,%2,%3};"
        : "+f"(c[0]), "+f"(c[1]), "+f"(c[2]), "+f"(c[3])
        : "r"(a[0]), "r"(a[1]), "r"(a[2]), "r"(a[3]), "r"(b0), "r"(b1));
}

// ---------------- init ----------------
__global__ void k_zero_counts() {
    int i = blockIdx.x * blockDim.x + threadIdx.x;
    if (i < NN) { g_deg[i] = 0; g_fill[i] = 0; }
}
__global__ void k_bnzero() {
    int i = threadIdx.x;
    if (i < HIDD) { g_bnsum[i] = 0.f; g_bnsq[i] = 0.f; }
}

// ---------------- CSR ----------------
__global__ void k_deg(const int* __restrict__ dst) {
    int e = blockIdx.x * blockDim.x + threadIdx.x;
    if (e < EE) atomicAdd(&g_deg[dst[e]], 1);
}

__global__ void k_scan() {   // 1 block, 1024 threads, warp-shuffle scan
    __shared__ int wsum[32];
    __shared__ int carry;
    int tid = threadIdx.x, lane = tid & 31, wid = tid >> 5;
    if (tid == 0) { carry = 0; g_rowptr[0] = 0; }
    __syncthreads();
    for (int base = 0; base < NN; base += 1024) {
        int v = (base + tid < NN) ? g_deg[base + tid] : 0;
        int s = v;
#pragma unroll
        for (int off = 1; off < 32; off <<= 1) {
            int t = __shfl_up_sync(~0u, s, off);
            if (lane >= off) s += t;
        }
        if (lane == 31) wsum[wid] = s;
        __syncthreads();
        if (wid == 0) {
            int ws = wsum[lane];
#pragma unroll
            for (int off = 1; off < 32; off <<= 1) {
                int t = __shfl_up_sync(~0u, ws, off);
                if (lane >= off) ws += t;
            }
            wsum[lane] = ws;
        }
        __syncthreads();
        int add = carry + (wid ? wsum[wid - 1] : 0);
        if (base + tid < NN) g_rowptr[base + tid + 1] = add + s;
        __syncthreads();
        if (tid == 0) carry += wsum[31];
        __syncthreads();
    }
}

__global__ void k_fill(const int* __restrict__ dst) {
    int e = blockIdx.x * blockDim.x + threadIdx.x;
    if (e < EE) {
        int d = dst[e];
        int p = atomicAdd(&g_fill[d], 1);
        g_col[g_rowptr[d] + p] = e;
    }
}

// ---------------- 3xTF32 tensor-core GEMM: C[M,Nn] = alpha*(A[M,K] @ B[K,Nn]) + bias ----------------
// BM=128, BN=64, BK=32, 256 threads (8 warps, 4x2), warp tile 32x32. K multiple of 32.
__global__ void __launch_bounds__(256) k_gemm_tf32(
    const float* __restrict__ A, const float* __restrict__ B,
    const float* __restrict__ bias, float* __restrict__ C,
    int M, int Nn, int K, float alpha)
{
    __shared__ float Ah[32][136];
    __shared__ float Al[32][136];
    __shared__ float Bs[32][72];

    int tid = threadIdx.x;
    int warp = tid >> 5, lane = tid & 31;
    int wm = warp & 3, wn = warp >> 2;
    int m0 = wm * 32, n0 = wn * 32;
    int row0 = blockIdx.y * 128, col0 = blockIdx.x * 64;

    float acc[2][4][4];
#pragma unroll
    for (int a = 0; a < 2; a++)
#pragma unroll
        for (int b = 0; b < 4; b++)
#pragma unroll
            for (int c = 0; c < 4; c++) acc[a][b][c] = 0.f;

    int fr = lane >> 2, fc = lane & 3;

    for (int kt = 0; kt < K; kt += 32) {
        // A tile: r = tid&127, transposed split store
        int r = tid & 127;
        int gr = row0 + r;
#pragma unroll
        for (int i = 0; i < 4; i++) {
            int c4 = (tid >> 7) + 2 * i;
            float4 v = make_float4(0.f, 0.f, 0.f, 0.f);
            if (gr < M) v = *(const float4*)&A[(size_t)gr * K + kt + c4 * 4];
            const float* vp = &v.x;
#pragma unroll
            for (int j = 0; j < 4; j++) {
                float f = vp[j];
                uint32_t hb = f2tf32(f);
                float hf = __uint_as_float(hb);
                Ah[c4 * 4 + j][r] = hf;
                Al[c4 * 4 + j][r] = __uint_as_float(f2tf32(f - hf));
            }
        }
        // B tile
#pragma unroll
        for (int i = 0; i < 2; i++) {
            int kk = (tid >> 4) + 16 * i;
            float4 v = *(const float4*)&B[(size_t)(kt + kk) * Nn + col0 + (tid & 15) * 4];
            *(float4*)&Bs[kk][(tid & 15) * 4] = v;
        }
        __syncthreads();

#pragma unroll
        for (int ks = 0; ks < 4; ks++) {
            int kb = ks * 8;
            uint32_t ah[2][4], al[2][4];
#pragma unroll
            for (int mi = 0; mi < 2; mi++) {
                int mr = m0 + mi * 16;
                ah[mi][0] = __float_as_uint(Ah[kb + fc][mr + fr]);
                ah[mi][1] = __float_as_uint(Ah[kb + fc][mr + fr + 8]);
                ah[mi][2] = __float_as_uint(Ah[kb + fc + 4][mr + fr]);
                ah[mi][3] = __float_as_uint(Ah[kb + fc + 4][mr + fr + 8]);
                al[mi][0] = __float_as_uint(Al[kb + fc][mr + fr]);
                al[mi][1] = __float_as_uint(Al[kb + fc][mr + fr + 8]);
                al[mi][2] = __float_as_uint(Al[kb + fc + 4][mr + fr]);
                al[mi][3] = __float_as_uint(Al[kb + fc + 4][mr + fr + 8]);
            }
#pragma unroll
            for (int ni = 0; ni < 4; ni++) {
                int nc = n0 + ni * 8 + (lane >> 2);
                float b0f = Bs[kb + fc][nc];
                float b1f = Bs[kb + fc + 4][nc];
                uint32_t b0h = f2tf32(b0f);
                uint32_t b1h = f2tf32(b1f);
                uint32_t b0l = f2tf32(b0f - __uint_as_float(b0h));
                uint32_t b1l = f2tf32(b1f - __uint_as_float(b1h));
#pragma unroll
                for (int mi = 0; mi < 2; mi++) {
                    mma8(acc[mi][ni], ah[mi], b0l, b1l);
                    mma8(acc[mi][ni], al[mi], b0h, b1h);
                    mma8(acc[mi][ni], ah[mi], b0h, b1h);
                }
            }
        }
        __syncthreads();
    }

    // epilogue
#pragma unroll
    for (int mi = 0; mi < 2; mi++) {
#pragma unroll
        for (int ni = 0; ni < 4; ni++) {
            int cc0 = col0 + n0 + ni * 8 + (lane & 3) * 2;
            float bb0 = 0.f, bb1 = 0.f;
            if (bias) { bb0 = bias[cc0]; bb1 = bias[cc0 + 1]; }
            int rr = row0 + m0 + mi * 16 + (lane >> 2);
            if (rr < M) {
                float2 o = make_float2(alpha * acc[mi][ni][0] + bb0, alpha * acc[mi][ni][1] + bb1);
                *(float2*)&C[(size_t)rr * Nn + cc0] = o;
            }
            if (rr + 8 < M) {
                float2 o = make_float2(alpha * acc[mi][ni][2] + bb0, alpha * acc[mi][ni][3] + bb1);
                *(float2*)&C[(size_t)(rr + 8) * Nn + cc0] = o;
            }
        }
    }
}

// ---------------- folded attention weights ----------------
__global__ void k_ve(const float* __restrict__ We, const float* __restrict__ att_edge) {
    int t = blockIdx.x * blockDim.x + threadIdx.x;
    if (t >= NL * HIDD * NH) return;
    int h = t & 3, k = (t >> 2) & 127, l = t >> 9;
    const float* w = We + (size_t)l * HIDD * (NH * HIDD) + (size_t)k * (NH * HIDD) + h * HIDD;
    const float* a = att_edge + (size_t)l * NH * HIDD + h * HIDD;
    float s = 0.f;
    for (int c = 0; c < HIDD; c++) s += w[c] * a[c];
    g_ve[t] = s;
}

__global__ void k_ue(const float* __restrict__ eenc_W, const float* __restrict__ eenc_b) {
    int t = blockIdx.x * blockDim.x + threadIdx.x;
    if (t < NL * 64 * NH) {
        int h = t & 3, j = (t >> 2) & 63, l = t >> 8;
        float s = 0.f;
        for (int k = 0; k < HIDD; k++) s += eenc_W[j * HIDD + k] * g_ve[l * 512 + k * 4 + h];
        g_ue[t] = s;
    } else if (t < NL * 64 * NH + NL * NH) {
        int q = t - NL * 64 * NH;
        int h = q & 3, l = q >> 2;
        float s = 0.f;
        for (int k = 0; k < HIDD; k++) s += eenc_b[k] * g_ve[l * 512 + k * 4 + h];
        g_ce[q] = s;
    }
}

__global__ void k_wsd(const float* __restrict__ W, const float* __restrict__ att_src,
                      const float* __restrict__ att_dst) {
    int t = blockIdx.x * blockDim.x + threadIdx.x;
    if (t >= NL * HIDD * 8) return;
    int o = t & 7, k = (t >> 3) & 127, l = t >> 10;
    int h = o & 3;
    const float* a = ((o < 4) ? att_src : att_dst) + ((size_t)l * 4 + h) * HIDD;
    const float* w = W + ((size_t)l * HIDD + k) * (NH * HIDD) + h * HIDD;
    float s = 0.f;
    for (int c = 0; c < HIDD; c++) s += w[c] * a[c];
    g_wsd[((size_t)l * HIDD + k) * 8 + o] = s;
}

// permute W: g_Wp[l][(h*128+c)][c'] = W[l][c][h*128+c']
__global__ void k_wperm(const float* __restrict__ W) {
    int t = blockIdx.x * blockDim.x + threadIdx.x;
    if (t >= NL * 512 * HIDD) return;
    int cp = t & 127;
    int k  = (t >> 7) & 511;
    int l  = t >> 16;
    int h = k >> 7, c = k & 127;
    g_Wp[t] = W[(size_t)l * HIDD * 512 + (size_t)c * 512 + h * HIDD + cp];
}

// edge logits: 4 edges/warp, 8 lanes each, weights register-resident
__global__ void __launch_bounds__(256) k_ae(const float* __restrict__ edge_attr) {
    int lane = threadIdx.x & 31;
    int kb = (lane & 7) * 8;
    float uw[8][8];
#pragma unroll
    for (int i = 0; i < 8; i++)
#pragma unroll
        for (int o = 0; o < 8; o++)
            uw[i][o] = g_ue[(o >> 2) * 256 + (kb + i) * 4 + (o & 3)];
    float cst = g_ce[lane & 7];

    int sub = lane >> 3;
    int warp = (blockIdx.x * blockDim.x + threadIdx.x) >> 5;
    int nw = (gridDim.x * blockDim.x) >> 5;
    for (int e4 = warp; e4 < EE / 4; e4 += nw) {
        int e = e4 * 4 + sub;
        float4 v0 = *(const float4*)&edge_attr[(size_t)e * 64 + kb];
        float4 v1 = *(const float4*)&edge_attr[(size_t)e * 64 + kb + 4];
        float p[8];
#pragma unroll
        for (int o = 0; o < 8; o++) {
            p[o] = v0.x * uw[0][o] + v0.y * uw[1][o] + v0.z * uw[2][o] + v0.w * uw[3][o]
                 + v1.x * uw[4][o] + v1.y * uw[5][o] + v1.z * uw[6][o] + v1.w * uw[7][o];
        }
#pragma unroll
        for (int off = 4; off; off >>= 1)
#pragma unroll
            for (int o = 0; o < 8; o++) p[o] += __shfl_xor_sync(~0u, p[o], off);
        g_ae[(size_t)e * 8 + (lane & 7)] = p[lane & 7] + cst;
    }
}

__global__ void k_aeloop() {
    int t = blockIdx.x * blockDim.x + threadIdx.x;
    if (t < NN * 8) {
        int n = t >> 3, o = t & 7;
        int r0 = g_rowptr[n], r1 = g_rowptr[n + 1];
        float s = 0.f;
        for (int i = r0; i < r1; i++) s += g_ae[(size_t)g_col[i] * 8 + o];
        g_aeloop[t] = s / fmaxf((float)(r1 - r0), 1.f);
    }
}

// a_src / a_dst = h @ g_wsd[l]   (warp per node)
__global__ void k_asd(int l) {
    int lane = threadIdx.x & 31;
    float wv[4][8];
#pragma unroll
    for (int j = 0; j < 4; j++)
#pragma unroll
        for (int o = 0; o < 8; o++)
            wv[j][o] = g_wsd[((size_t)l * HIDD + lane + 32 * j) * 8 + o];

    int warp = (blockIdx.x * blockDim.x + threadIdx.x) >> 5;
    int nw = (gridDim.x * blockDim.x) >> 5;
    for (int n = warp; n < NN; n += nw) {
        float p[8] = {0.f, 0.f, 0.f, 0.f, 0.f, 0.f, 0.f, 0.f};
#pragma unroll
        for (int j = 0; j < 4; j++) {
            float hv = g_h[(size_t)n * HIDD + lane + 32 * j];
#pragma unroll
            for (int o = 0; o < 8; o++) p[o] += hv * wv[j][o];
        }
#pragma unroll
        for (int off = 16; off; off >>= 1)
#pragma unroll
            for (int o = 0; o < 8; o++) p[o] += __shfl_xor_sync(~0u, p[o], off);
        if (lane < 4) g_asrc[n * 4 + lane] = p[lane];
        else if (lane < 8) g_adst[n * 4 + (lane - 4)] = p[lane];
    }
}

// ---------------- fused softmax + aggregation of h (pre-W) ----------------
// agg[n][h*128+c] = (Σ_e α_eh h[s][c] + wself_h h[n][c]) / denom_h
__global__ void __launch_bounds__(128) k_agg2(const int* __restrict__ srcArr, int l) {
    __shared__ float wbuf[512];
    __shared__ int   sbuf[128];
    __shared__ float sred[16];

    int n = blockIdx.x;
    int tid = threadIdx.x, lane = tid & 31, wid = tid >> 5;
    int row = g_rowptr[n];
    int deg = g_rowptr[n + 1] - row;

    float ad[4], wself[4];
#pragma unroll
    for (int h = 0; h < 4; h++) ad[h] = g_adst[n * 4 + h];
#pragma unroll
    for (int h = 0; h < 4; h++) {
        float a = g_asrc[n * 4 + h] + ad[h] + g_aeloop[n * 8 + l * 4 + h];
        a = (a >= 0.f) ? a : NEG * a;
        wself[h] = __expf(a);
    }

    float acc[4] = {0.f, 0.f, 0.f, 0.f};
    float sw[4] = {0.f, 0.f, 0.f, 0.f};
    for (int base = 0; base < deg; base += 128) {
        int i = base + tid;
        if (i < deg) {
            int e = g_col[row + i];
            int s = srcArr[e];
            sbuf[tid] = s;
#pragma unroll
            for (int h = 0; h < 4; h++) {
                float a = g_asrc[s * 4 + h] + ad[h] + g_ae[(size_t)e * 8 + l * 4 + h];
                a = (a >= 0.f) ? a : NEG * a;
                float ww = __expf(a);
                wbuf[tid * 4 + h] = ww;
                sw[h] += ww;
            }
        }
        __syncthreads();
        int cnt = min(128, deg - base);
        for (int j = 0; j < cnt; j++) {
            float hv = g_h[(size_t)sbuf[j] * HIDD + tid];
            float4 w4 = *(const float4*)&wbuf[j * 4];
            acc[0] += w4.x * hv; acc[1] += w4.y * hv;
            acc[2] += w4.z * hv; acc[3] += w4.w * hv;
        }
        __syncthreads();
    }

    // reduce sum-of-weights across the block
#pragma unroll
    for (int h = 0; h < 4; h++)
#pragma unroll
        for (int off = 16; off; off >>= 1) sw[h] += __shfl_xor_sync(~0u, sw[h], off);
    if (lane == 0) {
#pragma unroll
        for (int h = 0; h < 4; h++) sred[wid * 4 + h] = sw[h];
    }
    __syncthreads();
    float denom[4];
#pragma unroll
    for (int h = 0; h < 4; h++)
        denom[h] = sred[h] + sred[4 + h] + sred[8 + h] + sred[12 + h] + wself[h] + 1e-16f;

    float hself = g_h[(size_t)n * HIDD + tid];
#pragma unroll
    for (int h = 0; h < 4; h++) {
        float v = (acc[h] + wself[h] * hself) / denom[h];
        g_agg[(size_t)n * 512 + h * HIDD + tid] = v;
    }
}

// ---------------- batchnorm ----------------
__global__ void k_bnreduce() {
    int c = threadIdx.x;
    int rows_per = (NN + gridDim.x - 1) / gridDim.x;
    int r0 = blockIdx.x * rows_per;
    int r1 = min(NN, r0 + rows_per);
    float s = 0.f, q = 0.f;
    for (int r = r0; r < r1; r++) {
        float v = g_outp[r * 128 + c];
        s += v; q += v * v;
    }
    atomicAdd(&g_bnsum[c], s);
    atomicAdd(&g_bnsq[c], q);
}

__global__ void k_bnapply(const float* __restrict__ gamma, const float* __restrict__ beta,
                          float* __restrict__ out, int writeOut) {
    int i = blockIdx.x * blockDim.x + threadIdx.x;
    if (i < NN * 128) {
        int c = i & 127;
        float mu = g_bnsum[c] * (1.f / NN);
        float var = g_bnsq[c] * (1.f / NN) - mu * mu;
        float v = (g_outp[i] - mu) * rsqrtf(var + BNEPS) * gamma[c] + beta[c];
        float r = fmaxf(v, 0.f) + g_h[i];
        g_h[i] = r;
        if (writeOut) out[i] = r;
    }
}

// ---------------- launch ----------------
extern "C" void kernel_launch(void* const* d_in, const int* in_sizes, int n_in,
                              void* d_out, int out_size) {
    (void)in_sizes; (void)n_in; (void)out_size;
    const float* x        = (const float*)d_in[0];
    const int*   ei       = (const int*)d_in[1];
    const float* eattr    = (const float*)d_in[2];
    const float* encW     = (const float*)d_in[4];
    const float* encb     = (const float*)d_in[5];
    const float* eencW    = (const float*)d_in[6];
    const float* eencb    = (const float*)d_in[7];
    const float* W        = (const float*)d_in[8];
    const float* We       = (const float*)d_in[9];
    const float* att_src  = (const float*)d_in[10];
    const float* att_dst  = (const float*)d_in[11];
    const float* att_edge = (const float*)d_in[12];
    const float* bias     = (const float*)d_in[13];
    const float* gamma    = (const float*)d_in[14];
    const float* beta     = (const float*)d_in[15];
    const int* src = ei;
    const int* dst = ei + EE;

    float *p_h, *p_agg, *p_outp, *p_Wp;
    cudaGetSymbolAddress((void**)&p_h, g_h);
    cudaGetSymbolAddress((void**)&p_agg, g_agg);
    cudaGetSymbolAddress((void**)&p_outp, g_outp);
    cudaGetSymbolAddress((void**)&p_Wp, g_Wp);

    // CSR
    k_zero_counts<<<(NN + 255) / 256, 256>>>();
    k_deg<<<(EE + 255) / 256, 256>>>(dst);
    k_scan<<<1, 1024>>>();
    k_fill<<<(EE + 255) / 256, 256>>>(dst);

    // folded weights
    k_ve<<<(NL * HIDD * NH + 255) / 256, 256>>>(We, att_edge);
    k_ue<<<(NL * 64 * NH + NL * NH + 255) / 256, 256>>>(eencW, eencb);
    k_wsd<<<(NL * HIDD * 8 + 255) / 256, 256>>>(W, att_src, att_dst);
    k_wperm<<<(NL * 512 * HIDD + 255) / 256, 256>>>(W);

    // edge logits (both layers) + self-loop means
    k_ae<<<1024, 256>>>(eattr);
    k_aeloop<<<(NN * 8 + 255) / 256, 256>>>();

    // encoder: h = x @ enc_W + enc_b
    k_gemm_tf32<<<dim3(2, (NN + 127) / 128), 256>>>(x, encW, encb, p_h, NN, 128, 128, 1.f);

    for (int l = 0; l < NL; l++) {
        k_asd<<<160, 256>>>(l);
        k_agg2<<<NN, 128>>>(src, l);
        // out = 0.25 * agg[N,512] @ Wp[512,128] + bias
        k_gemm_tf32<<<dim3(2, (NN + 127) / 128), 256>>>(
            p_agg, p_Wp + (size_t)l * 512 * HIDD, bias + l * HIDD, p_outp,
            NN, 128, 512, 0.25f);
        k_bnzero<<<1, 128>>>();
        k_bnreduce<<<80, 128>>>();
        k_bnapply<<<(NN * 128 + 255) / 256, 256>>>(
            gamma + l * HIDD, beta + l * HIDD, (float*)d_out, (l == NL - 1) ? 1 : 0);
    }
}